// round 1
// baseline (speedup 1.0000x reference)
#include <cuda_runtime.h>
#include <math_constants.h>

#define BATCH 2
#define SEQ   4096
#define DIM   512

// ---------------- scratch (allocation-free: __device__ globals) ----------------
__device__ float g_q[(size_t)BATCH * SEQ * DIM];                 // 16 MB
__device__ float g_k[(size_t)BATCH * SEQ * DIM];                 // 16 MB
__device__ float g_sc[(size_t)BATCH * SEQ * SEQ];                // 134 MB

// ---------------- tiled fp32 GEMM ----------------
// C[M,N] = A[M,K] * B            (TRANSB=false: B is [K,N] row-major)
// C[M,N] = A[M,K] * B^T          (TRANSB=true : B is [N,K] row-major)
// BM=BN=128, BK=8, 256 threads, 8x8 per-thread microtile in 2x2 blocks of 4x4
// (split-column layout -> conflict-free LDS.128).
template <bool TRANSB>
__global__ void __launch_bounds__(256, 2) gemm_kernel(
    const float* __restrict__ A, const float* __restrict__ B, float* __restrict__ C,
    int M, int N, int K,
    long long strideA, long long strideB, long long strideC)
{
    constexpr int BM = 128, BN = 128, BK = 8;

    const int bz = blockIdx.z;
    A += (size_t)bz * strideA;
    B += (size_t)bz * strideB;
    C += (size_t)bz * strideC;

    const int bm = blockIdx.y * BM;
    const int bn = blockIdx.x * BN;

    __shared__ float As[BK][BM];
    __shared__ float Bs[BK][BN];

    const int tid = threadIdx.x;
    // A-tile loader (also used for B when TRANSB): 128 rows x 8 cols, one float4/thread
    const int lrow  = tid >> 1;          // 0..127
    const int lcolv = (tid & 1) * 4;     // 0 or 4
    // B-tile loader (NN): 8 rows x 128 cols
    const int brow  = tid >> 5;          // 0..7
    const int bcol  = (tid & 31) * 4;    // 0..124

    const int tx = tid & 15;             // 0..15 -> N
    const int ty = tid >> 4;             // 0..15 -> M

    float acc[2][2][4][4];
    #pragma unroll
    for (int a = 0; a < 2; a++)
        #pragma unroll
        for (int b = 0; b < 2; b++)
            #pragma unroll
            for (int i = 0; i < 4; i++)
                #pragma unroll
                for (int j = 0; j < 4; j++)
                    acc[a][b][i][j] = 0.0f;

    for (int k0 = 0; k0 < K; k0 += BK) {
        // load A tile (transposed into As[k][m])
        {
            float4 av = *(const float4*)(A + (size_t)(bm + lrow) * K + k0 + lcolv);
            As[lcolv + 0][lrow] = av.x;
            As[lcolv + 1][lrow] = av.y;
            As[lcolv + 2][lrow] = av.z;
            As[lcolv + 3][lrow] = av.w;
        }
        // load B tile
        if (TRANSB) {
            float4 bv = *(const float4*)(B + (size_t)(bn + lrow) * K + k0 + lcolv);
            Bs[lcolv + 0][lrow] = bv.x;
            Bs[lcolv + 1][lrow] = bv.y;
            Bs[lcolv + 2][lrow] = bv.z;
            Bs[lcolv + 3][lrow] = bv.w;
        } else {
            float4 bv = *(const float4*)(B + (size_t)(k0 + brow) * N + bn + bcol);
            *(float4*)&Bs[brow][bcol] = bv;
        }
        __syncthreads();

        #pragma unroll
        for (int kk = 0; kk < BK; kk++) {
            float ra[2][4], rb[2][4];
            #pragma unroll
            for (int h = 0; h < 2; h++) {
                float4 va = *(const float4*)&As[kk][h * 64 + ty * 4];
                ra[h][0] = va.x; ra[h][1] = va.y; ra[h][2] = va.z; ra[h][3] = va.w;
                float4 vb = *(const float4*)&Bs[kk][h * 64 + tx * 4];
                rb[h][0] = vb.x; rb[h][1] = vb.y; rb[h][2] = vb.z; rb[h][3] = vb.w;
            }
            #pragma unroll
            for (int a = 0; a < 2; a++)
                #pragma unroll
                for (int b = 0; b < 2; b++)
                    #pragma unroll
                    for (int i = 0; i < 4; i++)
                        #pragma unroll
                        for (int j = 0; j < 4; j++)
                            acc[a][b][i][j] += ra[a][i] * rb[b][j];
        }
        __syncthreads();
    }

    // writeback: 2x2 blocks of 4x4, float4 stores
    #pragma unroll
    for (int a = 0; a < 2; a++)
        #pragma unroll
        for (int i = 0; i < 4; i++) {
            const size_t row = (size_t)(bm + a * 64 + ty * 4 + i);
            #pragma unroll
            for (int b = 0; b < 2; b++) {
                float4 v;
                v.x = acc[a][b][i][0]; v.y = acc[a][b][i][1];
                v.z = acc[a][b][i][2]; v.w = acc[a][b][i][3];
                *(float4*)(C + row * N + bn + b * 64 + tx * 4) = v;
            }
        }
}

// ---------------- row softmax over SEQ=4096, one block per row ----------------
__global__ void __launch_bounds__(256) softmax_kernel(float* __restrict__ sc)
{
    const size_t row = blockIdx.x;
    float* p = sc + row * (size_t)SEQ;
    const int tid = threadIdx.x;

    float4 v[4];
    float m = -CUDART_INF_F;
    #pragma unroll
    for (int i = 0; i < 4; i++) {
        v[i] = *(const float4*)(p + (size_t)i * 1024 + tid * 4);
        m = fmaxf(m, fmaxf(fmaxf(v[i].x, v[i].y), fmaxf(v[i].z, v[i].w)));
    }

    __shared__ float sred[8];
    #pragma unroll
    for (int o = 16; o > 0; o >>= 1) m = fmaxf(m, __shfl_xor_sync(0xffffffffu, m, o));
    if ((tid & 31) == 0) sred[tid >> 5] = m;
    __syncthreads();
    float rmax = sred[0];
    #pragma unroll
    for (int i = 1; i < 8; i++) rmax = fmaxf(rmax, sred[i]);
    __syncthreads();

    float s = 0.0f;
    #pragma unroll
    for (int i = 0; i < 4; i++) {
        v[i].x = expf(v[i].x - rmax);
        v[i].y = expf(v[i].y - rmax);
        v[i].z = expf(v[i].z - rmax);
        v[i].w = expf(v[i].w - rmax);
        s += (v[i].x + v[i].y) + (v[i].z + v[i].w);
    }
    #pragma unroll
    for (int o = 16; o > 0; o >>= 1) s += __shfl_xor_sync(0xffffffffu, s, o);
    if ((tid & 31) == 0) sred[tid >> 5] = s;
    __syncthreads();
    float rsum = 0.0f;
    #pragma unroll
    for (int i = 0; i < 8; i++) rsum += sred[i];

    const float inv = 1.0f / rsum;
    #pragma unroll
    for (int i = 0; i < 4; i++) {
        v[i].x *= inv; v[i].y *= inv; v[i].z *= inv; v[i].w *= inv;
        *(float4*)(p + (size_t)i * 1024 + tid * 4) = v[i];
    }
}

// ---------------- launch ----------------
extern "C" void kernel_launch(void* const* d_in, const int* in_sizes, int n_in,
                              void* d_out, int out_size)
{
    const float* query = (const float*)d_in[0];
    const float* key   = (const float*)d_in[1];
    const float* Wq    = (const float*)d_in[2];
    const float* Wk    = (const float*)d_in[3];
    float* out = (float*)d_out;

    float *q, *k, *sc;
    cudaGetSymbolAddress((void**)&q,  g_q);
    cudaGetSymbolAddress((void**)&k,  g_k);
    cudaGetSymbolAddress((void**)&sc, g_sc);

    const long long sQK = (long long)SEQ * DIM;     // per-batch stride of [S,D] tensors
    const long long sSC = (long long)SEQ * SEQ;     // per-batch stride of scores

    dim3 blk(256);

    // q = query @ W_q   ;   k = key @ W_k
    gemm_kernel<false><<<dim3(DIM / 128, SEQ / 128, BATCH), blk>>>(
        query, Wq, q, SEQ, DIM, DIM, sQK, 0, sQK);
    gemm_kernel<false><<<dim3(DIM / 128, SEQ / 128, BATCH), blk>>>(
        key, Wk, k, SEQ, DIM, DIM, sQK, 0, sQK);

    // scores = q @ k^T
    gemm_kernel<true><<<dim3(SEQ / 128, SEQ / 128, BATCH), blk>>>(
        q, k, sc, SEQ, SEQ, DIM, sQK, sQK, sSC);

    // softmax rows
    softmax_kernel<<<BATCH * SEQ, 256>>>(sc);

    // out = weights @ key   (V = raw key)
    gemm_kernel<false><<<dim3(DIM / 128, SEQ / 128, BATCH), blk>>>(
        sc, key, out, SEQ, DIM, SEQ, sSC, sQK, sQK);
}

// round 6
// speedup vs baseline: 2.4391x; 2.4391x over previous
#include <cuda_runtime.h>
#include <cuda_fp16.h>
#include <math_constants.h>
#include <cstdint>
#include <cstddef>

#define BATCH 2
#define SEQ   4096
#define DIM   512

// ---------------- scratch (allocation-free: __device__ globals) ----------------
__device__ __half g_qry_h[(size_t)BATCH * SEQ * DIM];
__device__ __half g_qry_l[(size_t)BATCH * SEQ * DIM];
__device__ __half g_key_h[(size_t)BATCH * SEQ * DIM];
__device__ __half g_key_l[(size_t)BATCH * SEQ * DIM];
__device__ __half g_wqt_h[(size_t)DIM * DIM];
__device__ __half g_wqt_l[(size_t)DIM * DIM];
__device__ __half g_wkt_h[(size_t)DIM * DIM];
__device__ __half g_wkt_l[(size_t)DIM * DIM];
__device__ __half g_keyT_h[(size_t)BATCH * DIM * SEQ];
__device__ __half g_keyT_l[(size_t)BATCH * DIM * SEQ];
__device__ __half g_q_h[(size_t)BATCH * SEQ * DIM];
__device__ __half g_q_l[(size_t)BATCH * SEQ * DIM];
__device__ __half g_k_h[(size_t)BATCH * SEQ * DIM];
__device__ __half g_k_l[(size_t)BATCH * SEQ * DIM];
__device__ float  g_sc [(size_t)BATCH * SEQ * SEQ];
__device__ __half g_w_h[(size_t)BATCH * SEQ * SEQ];
__device__ __half g_w_l[(size_t)BATCH * SEQ * SEQ];

// ---------------- helpers ----------------
__device__ __forceinline__ uint32_t s2u(const void* p) {
    uint32_t a;
    asm("{ .reg .u64 t; cvta.to.shared.u64 t, %1; cvt.u32.u64 %0, t; }" : "=r"(a) : "l"(p));
    return a;
}

__device__ __forceinline__ void ldsm_x4(uint32_t& r0, uint32_t& r1, uint32_t& r2, uint32_t& r3,
                                        uint32_t addr) {
    asm volatile("ldmatrix.sync.aligned.m8n8.x4.shared.b16 {%0,%1,%2,%3}, [%4];"
                 : "=r"(r0), "=r"(r1), "=r"(r2), "=r"(r3) : "r"(addr));
}

__device__ __forceinline__ void mma16816(float* d, const uint32_t* a, const uint32_t* b) {
    asm volatile(
        "mma.sync.aligned.m16n8k16.row.col.f32.f16.f16.f32 "
        "{%0,%1,%2,%3},{%4,%5,%6,%7},{%8,%9},{%0,%1,%2,%3};"
        : "+f"(d[0]), "+f"(d[1]), "+f"(d[2]), "+f"(d[3])
        : "r"(a[0]), "r"(a[1]), "r"(a[2]), "r"(a[3]), "r"(b[0]), "r"(b[1]));
}

__device__ __forceinline__ void split_h(float v, __half& h, __half& l) {
    h = __float2half_rn(v);
    l = __float2half_rn(v - __half2float(h));
}

// ---------------- prep kernels ----------------
__global__ void split_kernel(const float* __restrict__ in, __half* __restrict__ oh,
                             __half* __restrict__ ol, size_t n) {
    for (size_t i = (size_t)blockIdx.x * blockDim.x + threadIdx.x; i < n;
         i += (size_t)gridDim.x * blockDim.x) {
        __half h, l; split_h(in[i], h, l);
        oh[i] = h; ol[i] = l;
    }
}

// out[c][r] = in[r][c], fp16 hi/lo split. in: [R,C] row-major, out: [C,R].
__global__ void transpose_split_kernel(const float* __restrict__ in, __half* __restrict__ oh,
                                       __half* __restrict__ ol, int R, int C,
                                       long long sIn, long long sOut) {
    __shared__ float t[32][33];
    const int bz = blockIdx.z;
    in += (size_t)bz * sIn;
    oh += (size_t)bz * sOut;
    ol += (size_t)bz * sOut;
    const int c0 = blockIdx.x * 32, r0 = blockIdx.y * 32;
    const int tx = threadIdx.x, ty = threadIdx.y;  // 32 x 8
    #pragma unroll
    for (int j = 0; j < 32; j += 8)
        t[ty + j][tx] = in[(size_t)(r0 + ty + j) * C + c0 + tx];
    __syncthreads();
    #pragma unroll
    for (int j = 0; j < 32; j += 8) {
        size_t idx = (size_t)(c0 + ty + j) * R + r0 + tx;
        __half h, l; split_h(t[tx][ty + j], h, l);
        oh[idx] = h; ol[idx] = l;
    }
}

// ---------------- mma.sync fp16 GEMM:  C[M,N] = A[M,K] * B[N,K]^T -------------
// A,B are exact (hi,lo) fp16 splits. 3 compensated passes: hh + hl + lh.
// Cf != nullptr -> fp32 out; else fp16 split to (Ch, Cl).
#define BM 128
#define BN 128
#define BK 32
#define STAGES 3
#define ATILE_B (BM * BK * 2)            // 8 KB (fp16)
#define STAGE_B (4 * ATILE_B)            // Ah, Al, Bh, Bl = 32 KB
#define DYN_SMEM (STAGES * STAGE_B)      // 96 KB

// swizzled byte offset of 16B chunk (row, ch) in a [rows][32 fp16] tile (64B rows)
__device__ __forceinline__ uint32_t sw_off(int row, int ch) {
    return (uint32_t)(row * 64 + ((ch ^ ((row >> 1) & 3)) << 4));
}

__global__ void __launch_bounds__(256, 1) gemm_mma(
    const __half* __restrict__ Ah, const __half* __restrict__ Al,
    const __half* __restrict__ Bh, const __half* __restrict__ Bl,
    float* __restrict__ Cf, __half* __restrict__ Ch, __half* __restrict__ Cl,
    int M, int N, int K, long long sA, long long sB, long long sC)
{
    extern __shared__ char smem[];
    const int tid  = threadIdx.x;
    const int lane = tid & 31;
    const int wid  = tid >> 5;
    const int wm   = wid & 3;      // 4 warps over M -> 32 rows each
    const int wn   = wid >> 2;     // 2 warps over N -> 64 cols each
    const int bz = blockIdx.z;
    Ah += (size_t)bz * sA; Al += (size_t)bz * sA;
    Bh += (size_t)bz * sB; Bl += (size_t)bz * sB;
    if (Cf) Cf += (size_t)bz * sC;
    if (Ch) { Ch += (size_t)bz * sC; Cl += (size_t)bz * sC; }
    const int bm = blockIdx.y * BM;
    const int bn = blockIdx.x * BN;
    const uint32_t sbase = s2u(smem);
    const int NC = K / BK;

    float acc[2][8][4];
    #pragma unroll
    for (int a = 0; a < 2; a++)
        #pragma unroll
        for (int b = 0; b < 8; b++)
            #pragma unroll
            for (int c = 0; c < 4; c++) acc[a][b][c] = 0.0f;

    // ---- loader: 4 tiles x 512 16B-chunks; 256 threads x 8 ----
    auto load_chunk = [&](int chunk) {
        const uint32_t sb = sbase + (chunk % STAGES) * STAGE_B;
        #pragma unroll
        for (int j = 0; j < 8; j++) {
            int g = tid + 256 * j;
            int t = g >> 9;            // tile 0..3
            int u = g & 511;
            int row = u >> 2;
            int c = u & 3;
            const __half* base = (t == 0) ? Ah : (t == 1) ? Al : (t == 2) ? Bh : Bl;
            int rbase = (t < 2) ? bm : bn;
            const __half* src = base + (size_t)(rbase + row) * K + chunk * BK + c * 8;
            uint32_t dst = sb + t * ATILE_B + sw_off(row, c);
            asm volatile("cp.async.cg.shared.global [%0], [%1], 16;" :: "r"(dst), "l"(src));
        }
        asm volatile("cp.async.commit_group;" ::: "memory");
    };

    load_chunk(0);
    if (NC > 1) load_chunk(1); else asm volatile("cp.async.commit_group;" ::: "memory");

    for (int i = 0; i < NC; i++) {
        asm volatile("cp.async.wait_group 1;" ::: "memory");
        __syncthreads();
        if (i + 2 < NC) load_chunk(i + 2);
        else asm volatile("cp.async.commit_group;" ::: "memory");

        const uint32_t sb = sbase + (i % STAGES) * STAGE_B;
        const uint32_t sAh = sb;
        const uint32_t sAl = sb + ATILE_B;
        const uint32_t sBh = sb + 2 * ATILE_B;
        const uint32_t sBl = sb + 3 * ATILE_B;
        const int q = lane >> 3, r = lane & 7;

        #pragma unroll
        for (int ks = 0; ks < 2; ks++) {
            uint32_t a_h[2][4], a_l[2][4], b_h[8][2], b_l[8][2];
            // A frags: mats (m0-7,klo)(m8-15,klo)(m0-7,khi)(m8-15,khi)
            #pragma unroll
            for (int mf = 0; mf < 2; mf++) {
                int row = wm * 32 + mf * 16 + ((q & 1) << 3) + r;
                int ch  = 2 * ks + (q >> 1);
                uint32_t ad = sw_off(row, ch);
                ldsm_x4(a_h[mf][0], a_h[mf][1], a_h[mf][2], a_h[mf][3], sAh + ad);
                ldsm_x4(a_l[mf][0], a_l[mf][1], a_l[mf][2], a_l[mf][3], sAl + ad);
            }
            // B frags: mats (n0-7,klo)(n0-7,khi)(n8-15,klo)(n8-15,khi)
            #pragma unroll
            for (int np = 0; np < 4; np++) {
                int row = wn * 64 + np * 16 + ((q >> 1) << 3) + r;
                int ch  = 2 * ks + (q & 1);
                uint32_t bd = sw_off(row, ch);
                ldsm_x4(b_h[2 * np][0], b_h[2 * np][1], b_h[2 * np + 1][0], b_h[2 * np + 1][1],
                        sBh + bd);
                ldsm_x4(b_l[2 * np][0], b_l[2 * np][1], b_l[2 * np + 1][0], b_l[2 * np + 1][1],
                        sBl + bd);
            }
            #pragma unroll
            for (int mf = 0; mf < 2; mf++)
                #pragma unroll
                for (int nf = 0; nf < 8; nf++) {
                    mma16816(acc[mf][nf], a_h[mf], b_h[nf]);
                    mma16816(acc[mf][nf], a_h[mf], b_l[nf]);
                    mma16816(acc[mf][nf], a_l[mf], b_h[nf]);
                }
        }
        __syncthreads();
    }

    // ---- epilogue: fragment direct stores ----
    const int lr = lane >> 2;          // 0..7
    const int lc = (lane & 3) * 2;     // 0,2,4,6
    #pragma unroll
    for (int mf = 0; mf < 2; mf++) {
        #pragma unroll
        for (int nf = 0; nf < 8; nf++) {
            int row0 = bm + wm * 32 + mf * 16 + lr;
            int col  = bn + wn * 64 + nf * 8 + lc;
            float* d = acc[mf][nf];
            if (Cf) {
                *(float2*)&Cf[(size_t)row0 * N + col]       = make_float2(d[0], d[1]);
                *(float2*)&Cf[(size_t)(row0 + 8) * N + col] = make_float2(d[2], d[3]);
            } else {
                __half h0, l0, h1, l1;
                split_h(d[0], h0, l0); split_h(d[1], h1, l1);
                *(__half2*)&Ch[(size_t)row0 * N + col] = __halves2half2(h0, h1);
                *(__half2*)&Cl[(size_t)row0 * N + col] = __halves2half2(l0, l1);
                split_h(d[2], h0, l0); split_h(d[3], h1, l1);
                *(__half2*)&Ch[(size_t)(row0 + 8) * N + col] = __halves2half2(h0, h1);
                *(__half2*)&Cl[(size_t)(row0 + 8) * N + col] = __halves2half2(l0, l1);
            }
        }
    }
}

// ---------------- row softmax over SEQ=4096 -> fp16 split weights ----------------
__global__ void __launch_bounds__(256) softmax_kernel(const float* __restrict__ sc,
                                                      __half* __restrict__ wh,
                                                      __half* __restrict__ wl)
{
    const size_t row = blockIdx.x;
    const float* p = sc + row * (size_t)SEQ;
    const int tid = threadIdx.x;

    float4 v[4];
    float m = -CUDART_INF_F;
    #pragma unroll
    for (int i = 0; i < 4; i++) {
        v[i] = *(const float4*)(p + (size_t)i * 1024 + tid * 4);
        m = fmaxf(m, fmaxf(fmaxf(v[i].x, v[i].y), fmaxf(v[i].z, v[i].w)));
    }

    __shared__ float sred[8];
    #pragma unroll
    for (int o = 16; o > 0; o >>= 1) m = fmaxf(m, __shfl_xor_sync(0xffffffffu, m, o));
    if ((tid & 31) == 0) sred[tid >> 5] = m;
    __syncthreads();
    float rmax = sred[0];
    #pragma unroll
    for (int i = 1; i < 8; i++) rmax = fmaxf(rmax, sred[i]);
    __syncthreads();

    float s = 0.0f;
    #pragma unroll
    for (int i = 0; i < 4; i++) {
        v[i].x = expf(v[i].x - rmax);
        v[i].y = expf(v[i].y - rmax);
        v[i].z = expf(v[i].z - rmax);
        v[i].w = expf(v[i].w - rmax);
        s += (v[i].x + v[i].y) + (v[i].z + v[i].w);
    }
    #pragma unroll
    for (int o = 16; o > 0; o >>= 1) s += __shfl_xor_sync(0xffffffffu, s, o);
    if ((tid & 31) == 0) sred[tid >> 5] = s;
    __syncthreads();
    float rsum = 0.0f;
    #pragma unroll
    for (int i = 0; i < 8; i++) rsum += sred[i];

    const float inv = 1.0f / rsum;
    __half* oh = wh + row * (size_t)SEQ;
    __half* ol = wl + row * (size_t)SEQ;
    #pragma unroll
    for (int i = 0; i < 4; i++) {
        float w0 = v[i].x * inv, w1 = v[i].y * inv, w2 = v[i].z * inv, w3 = v[i].w * inv;
        __half h0, l0, h1, l1, h2, l2, h3, l3;
        split_h(w0, h0, l0); split_h(w1, h1, l1);
        split_h(w2, h2, l2); split_h(w3, h3, l3);
        size_t idx = (size_t)i * 1024 + tid * 4;
        *(__half2*)&oh[idx]     = __halves2half2(h0, h1);
        *(__half2*)&oh[idx + 2] = __halves2half2(h2, h3);
        *(__half2*)&ol[idx]     = __halves2half2(l0, l1);
        *(__half2*)&ol[idx + 2] = __halves2half2(l2, l3);
    }
}

// ---------------- launch ----------------
extern "C" void kernel_launch(void* const* d_in, const int* in_sizes, int n_in,
                              void* d_out, int out_size)
{
    const float* query = (const float*)d_in[0];
    const float* key   = (const float*)d_in[1];
    const float* Wq    = (const float*)d_in[2];
    const float* Wk    = (const float*)d_in[3];
    float* out = (float*)d_out;

    __half *qry_h, *qry_l, *key_h, *key_l, *wqt_h, *wqt_l, *wkt_h, *wkt_l;
    __half *keyT_h, *keyT_l, *q_h, *q_l, *k_h, *k_l, *w_h, *w_l;
    float* sc;
    cudaGetSymbolAddress((void**)&qry_h,  g_qry_h);
    cudaGetSymbolAddress((void**)&qry_l,  g_qry_l);
    cudaGetSymbolAddress((void**)&key_h,  g_key_h);
    cudaGetSymbolAddress((void**)&key_l,  g_key_l);
    cudaGetSymbolAddress((void**)&wqt_h,  g_wqt_h);
    cudaGetSymbolAddress((void**)&wqt_l,  g_wqt_l);
    cudaGetSymbolAddress((void**)&wkt_h,  g_wkt_h);
    cudaGetSymbolAddress((void**)&wkt_l,  g_wkt_l);
    cudaGetSymbolAddress((void**)&keyT_h, g_keyT_h);
    cudaGetSymbolAddress((void**)&keyT_l, g_keyT_l);
    cudaGetSymbolAddress((void**)&q_h,    g_q_h);
    cudaGetSymbolAddress((void**)&q_l,    g_q_l);
    cudaGetSymbolAddress((void**)&k_h,    g_k_h);
    cudaGetSymbolAddress((void**)&k_l,    g_k_l);
    cudaGetSymbolAddress((void**)&sc,     g_sc);
    cudaGetSymbolAddress((void**)&w_h,    g_w_h);
    cudaGetSymbolAddress((void**)&w_l,    g_w_l);

    cudaFuncSetAttribute(gemm_mma, cudaFuncAttributeMaxDynamicSharedMemorySize, DYN_SMEM);

    const long long sQK = (long long)SEQ * DIM;
    const long long sSC = (long long)SEQ * SEQ;
    const long long sKT = (long long)DIM * SEQ;
    const size_t nQK = (size_t)BATCH * SEQ * DIM;

    // 1) fp16 splits of raw inputs
    split_kernel<<<4096, 256>>>(query, qry_h, qry_l, nQK);
    split_kernel<<<4096, 256>>>(key,   key_h, key_l, nQK);

    // 2) transposed + split W  (B operand must be [N,K] K-major)
    transpose_split_kernel<<<dim3(DIM / 32, DIM / 32, 1), dim3(32, 8)>>>(
        Wq, wqt_h, wqt_l, DIM, DIM, 0, 0);
    transpose_split_kernel<<<dim3(DIM / 32, DIM / 32, 1), dim3(32, 8)>>>(
        Wk, wkt_h, wkt_l, DIM, DIM, 0, 0);

    // 3) transposed + split key (V operand): keyT[d][s]
    transpose_split_kernel<<<dim3(DIM / 32, SEQ / 32, BATCH), dim3(32, 8)>>>(
        key, keyT_h, keyT_l, SEQ, DIM, sQK, sKT);

    // 4) projections (epilogue emits fp16 split)
    gemm_mma<<<dim3(DIM / BN, SEQ / BM, BATCH), 256, DYN_SMEM>>>(
        qry_h, qry_l, wqt_h, wqt_l, nullptr, q_h, q_l, SEQ, DIM, DIM, sQK, 0, sQK);
    gemm_mma<<<dim3(DIM / BN, SEQ / BM, BATCH), 256, DYN_SMEM>>>(
        key_h, key_l, wkt_h, wkt_l, nullptr, k_h, k_l, SEQ, DIM, DIM, sQK, 0, sQK);

    // 5) scores = q @ k^T (fp32)
    gemm_mma<<<dim3(SEQ / BN, SEQ / BM, BATCH), 256, DYN_SMEM>>>(
        q_h, q_l, k_h, k_l, sc, nullptr, nullptr, SEQ, SEQ, DIM, sQK, sQK, sSC);

    // 6) softmax -> split weights
    softmax_kernel<<<BATCH * SEQ, 256>>>(sc, w_h, w_l);

    // 7) out = weights @ key  (keyT as [N,K])
    gemm_mma<<<dim3(DIM / BN, SEQ / BM, BATCH), 256, DYN_SMEM>>>(
        w_h, w_l, keyT_h, keyT_l, out, nullptr, nullptr, SEQ, DIM, SEQ, sSC, sKT, sQK);
}

// round 7
// speedup vs baseline: 2.7513x; 1.1280x over previous
#include <cuda_runtime.h>
#include <cuda_fp16.h>
#include <math_constants.h>
#include <cstdint>
#include <cstddef>

#define BATCH 2
#define SEQ   4096
#define DIM   512

// ---------------- scratch (allocation-free: __device__ globals) ----------------
__device__ __half g_qry_h[(size_t)BATCH * SEQ * DIM];
__device__ __half g_qry_l[(size_t)BATCH * SEQ * DIM];
__device__ __half g_key_h[(size_t)BATCH * SEQ * DIM];
__device__ __half g_key_l[(size_t)BATCH * SEQ * DIM];
__device__ __half g_wqt_h[(size_t)DIM * DIM];
__device__ __half g_wqt_l[(size_t)DIM * DIM];
__device__ __half g_wkt_h[(size_t)DIM * DIM];
__device__ __half g_wkt_l[(size_t)DIM * DIM];
__device__ __half g_keyT_h[(size_t)BATCH * DIM * SEQ];
__device__ __half g_keyT_l[(size_t)BATCH * DIM * SEQ];
__device__ __half g_q_h[(size_t)BATCH * SEQ * DIM];
__device__ __half g_q_l[(size_t)BATCH * SEQ * DIM];
__device__ __half g_k_h[(size_t)BATCH * SEQ * DIM];
__device__ __half g_k_l[(size_t)BATCH * SEQ * DIM];
__device__ float  g_sc [(size_t)BATCH * SEQ * SEQ];
__device__ __half g_w_h[(size_t)BATCH * SEQ * SEQ];
__device__ __half g_w_l[(size_t)BATCH * SEQ * SEQ];

// ---------------- helpers ----------------
__device__ __forceinline__ uint32_t s2u(const void* p) {
    uint32_t a;
    asm("{ .reg .u64 t; cvta.to.shared.u64 t, %1; cvt.u32.u64 %0, t; }" : "=r"(a) : "l"(p));
    return a;
}

__device__ __forceinline__ void ldsm_x4(uint32_t& r0, uint32_t& r1, uint32_t& r2, uint32_t& r3,
                                        uint32_t addr) {
    asm volatile("ldmatrix.sync.aligned.m8n8.x4.shared.b16 {%0,%1,%2,%3}, [%4];"
                 : "=r"(r0), "=r"(r1), "=r"(r2), "=r"(r3) : "r"(addr));
}

__device__ __forceinline__ void mma16816(float* d, const uint32_t* a, const uint32_t* b) {
    asm volatile(
        "mma.sync.aligned.m16n8k16.row.col.f32.f16.f16.f32 "
        "{%0,%1,%2,%3},{%4,%5,%6,%7},{%8,%9},{%0,%1,%2,%3};"
        : "+f"(d[0]), "+f"(d[1]), "+f"(d[2]), "+f"(d[3])
        : "r"(a[0]), "r"(a[1]), "r"(a[2]), "r"(a[3]), "r"(b[0]), "r"(b[1]));
}

__device__ __forceinline__ void split_h(float v, __half& h, __half& l) {
    h = __float2half_rn(v);
    l = __float2half_rn(v - __half2float(h));
}

// ---------------- prep kernels ----------------
__global__ void split_kernel(const float* __restrict__ in, __half* __restrict__ oh,
                             __half* __restrict__ ol, size_t n) {
    for (size_t i = (size_t)blockIdx.x * blockDim.x + threadIdx.x; i < n;
         i += (size_t)gridDim.x * blockDim.x) {
        __half h, l; split_h(in[i], h, l);
        oh[i] = h; ol[i] = l;
    }
}

// out[c][r] = in[r][c], fp16 hi/lo split. in: [R,C] row-major, out: [C,R].
__global__ void transpose_split_kernel(const float* __restrict__ in, __half* __restrict__ oh,
                                       __half* __restrict__ ol, int R, int C,
                                       long long sIn, long long sOut) {
    __shared__ float t[32][33];
    const int bz = blockIdx.z;
    in += (size_t)bz * sIn;
    oh += (size_t)bz * sOut;
    ol += (size_t)bz * sOut;
    const int c0 = blockIdx.x * 32, r0 = blockIdx.y * 32;
    const int tx = threadIdx.x, ty = threadIdx.y;  // 32 x 8
    #pragma unroll
    for (int j = 0; j < 32; j += 8)
        t[ty + j][tx] = in[(size_t)(r0 + ty + j) * C + c0 + tx];
    __syncthreads();
    #pragma unroll
    for (int j = 0; j < 32; j += 8) {
        size_t idx = (size_t)(c0 + ty + j) * R + r0 + tx;
        __half h, l; split_h(t[tx][ty + j], h, l);
        oh[idx] = h; ol[idx] = l;
    }
}

// ---------------- mma.sync fp16 GEMM:  C[M,N] = A[M,K] * B[N,K]^T -------------
// A,B are exact (hi,lo) fp16 splits. 3 compensated passes: hh + hl + lh.
// Cf != nullptr -> fp32 out; else fp16 split to (Ch, Cl).
// 256x128 CTA tile, 512 threads (8 warps M x 2 warps N; warp tile 32x64).
#define BM 256
#define BN 128
#define BK 32
#define STAGES 3
#define ATILE_B (BM * BK * 2)            // 16 KB (fp16)
#define BTILE_B (BN * BK * 2)            // 8 KB
#define STAGE_B (2 * ATILE_B + 2 * BTILE_B)   // 48 KB
#define DYN_SMEM (STAGES * STAGE_B)           // 144 KB
#define NTHREADS 512

// swizzled byte offset of 16B chunk (row, ch) in a [rows][32 fp16] tile (64B rows)
__device__ __forceinline__ uint32_t sw_off(int row, int ch) {
    return (uint32_t)(row * 64 + ((ch ^ ((row >> 1) & 3)) << 4));
}

__global__ void __launch_bounds__(NTHREADS, 1) gemm_mma(
    const __half* __restrict__ Ah, const __half* __restrict__ Al,
    const __half* __restrict__ Bh, const __half* __restrict__ Bl,
    float* __restrict__ Cf, __half* __restrict__ Ch, __half* __restrict__ Cl,
    int M, int N, int K, long long sA, long long sB, long long sC)
{
    extern __shared__ char smem[];
    const int tid  = threadIdx.x;
    const int lane = tid & 31;
    const int wid  = tid >> 5;
    const int wm   = wid & 7;      // 8 warps over M -> 32 rows each
    const int wn   = wid >> 3;     // 2 warps over N -> 64 cols each
    const int bz = blockIdx.z;
    Ah += (size_t)bz * sA; Al += (size_t)bz * sA;
    Bh += (size_t)bz * sB; Bl += (size_t)bz * sB;
    if (Cf) Cf += (size_t)bz * sC;
    if (Ch) { Ch += (size_t)bz * sC; Cl += (size_t)bz * sC; }
    const int bm = blockIdx.y * BM;
    const int bn = blockIdx.x * BN;
    const uint32_t sbase = s2u(smem);
    const int NC = K / BK;

    float acc[2][8][4];
    #pragma unroll
    for (int a = 0; a < 2; a++)
        #pragma unroll
        for (int b = 0; b < 8; b++)
            #pragma unroll
            for (int c = 0; c < 4; c++) acc[a][b][c] = 0.0f;

    // ---- loader: Ah/Al 1024 16B-chunks each, Bh/Bl 512 each = 3072; 512 thr x 6 ----
    auto load_chunk = [&](int chunk) {
        const uint32_t sb = sbase + (chunk % STAGES) * STAGE_B;
        #pragma unroll
        for (int j = 0; j < 6; j++) {
            int g = tid + NTHREADS * j;     // 0..3071
            const __half* base;
            uint32_t dst;
            int row, c;
            if (g < 2048) {                 // A side
                int t = g >> 10;            // 0: Ah, 1: Al
                int u = g & 1023;
                row = u >> 2; c = u & 3;
                base = t ? Al : Ah;
                dst = sb + t * ATILE_B + sw_off(row, c);
                base += (size_t)(bm + row) * K + chunk * BK + c * 8;
            } else {                        // B side
                int b2 = g - 2048;
                int t = b2 >> 9;            // 0: Bh, 1: Bl
                int u = b2 & 511;
                row = u >> 2; c = u & 3;
                base = t ? Bl : Bh;
                dst = sb + 2 * ATILE_B + t * BTILE_B + sw_off(row, c);
                base += (size_t)(bn + row) * K + chunk * BK + c * 8;
            }
            asm volatile("cp.async.cg.shared.global [%0], [%1], 16;" :: "r"(dst), "l"(base));
        }
        asm volatile("cp.async.commit_group;" ::: "memory");
    };

    load_chunk(0);
    if (NC > 1) load_chunk(1); else asm volatile("cp.async.commit_group;" ::: "memory");

    for (int i = 0; i < NC; i++) {
        asm volatile("cp.async.wait_group 1;" ::: "memory");
        __syncthreads();
        if (i + 2 < NC) load_chunk(i + 2);
        else asm volatile("cp.async.commit_group;" ::: "memory");

        const uint32_t sb  = sbase + (i % STAGES) * STAGE_B;
        const uint32_t sAh = sb;
        const uint32_t sAl = sb + ATILE_B;
        const uint32_t sBh = sb + 2 * ATILE_B;
        const uint32_t sBl = sb + 2 * ATILE_B + BTILE_B;
        const int q = lane >> 3, r = lane & 7;

        #pragma unroll
        for (int ks = 0; ks < 2; ks++) {
            uint32_t a_h[2][4], a_l[2][4];
            // A frags: mats (m0-7,klo)(m8-15,klo)(m0-7,khi)(m8-15,khi)
            #pragma unroll
            for (int mf = 0; mf < 2; mf++) {
                int row = wm * 32 + mf * 16 + ((q & 1) << 3) + r;
                int ch  = 2 * ks + (q >> 1);
                uint32_t ad = sw_off(row, ch);
                ldsm_x4(a_h[mf][0], a_h[mf][1], a_h[mf][2], a_h[mf][3], sAh + ad);
                ldsm_x4(a_l[mf][0], a_l[mf][1], a_l[mf][2], a_l[mf][3], sAl + ad);
            }
            // B frags streamed per 16-col group to bound register pressure
            #pragma unroll
            for (int np = 0; np < 4; np++) {
                uint32_t b_h[2][2], b_l[2][2];
                int row = wn * 64 + np * 16 + ((q >> 1) << 3) + r;
                int ch  = 2 * ks + (q & 1);
                uint32_t bd = sw_off(row, ch);
                ldsm_x4(b_h[0][0], b_h[0][1], b_h[1][0], b_h[1][1], sBh + bd);
                ldsm_x4(b_l[0][0], b_l[0][1], b_l[1][0], b_l[1][1], sBl + bd);
                #pragma unroll
                for (int mf = 0; mf < 2; mf++)
                    #pragma unroll
                    for (int nn = 0; nn < 2; nn++) {
                        float* d = acc[mf][2 * np + nn];
                        mma16816(d, a_h[mf], b_h[nn]);
                        mma16816(d, a_h[mf], b_l[nn]);
                        mma16816(d, a_l[mf], b_h[nn]);
                    }
            }
        }
        __syncthreads();
    }

    // ---- epilogue: fragment direct stores ----
    const int lr = lane >> 2;          // 0..7
    const int lc = (lane & 3) * 2;     // 0,2,4,6
    #pragma unroll
    for (int mf = 0; mf < 2; mf++) {
        #pragma unroll
        for (int nf = 0; nf < 8; nf++) {
            int row0 = bm + wm * 32 + mf * 16 + lr;
            int col  = bn + wn * 64 + nf * 8 + lc;
            float* d = acc[mf][nf];
            if (Cf) {
                *(float2*)&Cf[(size_t)row0 * N + col]       = make_float2(d[0], d[1]);
                *(float2*)&Cf[(size_t)(row0 + 8) * N + col] = make_float2(d[2], d[3]);
            } else {
                __half h0, l0, h1, l1;
                split_h(d[0], h0, l0); split_h(d[1], h1, l1);
                *(__half2*)&Ch[(size_t)row0 * N + col] = __halves2half2(h0, h1);
                *(__half2*)&Cl[(size_t)row0 * N + col] = __halves2half2(l0, l1);
                split_h(d[2], h0, l0); split_h(d[3], h1, l1);
                *(__half2*)&Ch[(size_t)(row0 + 8) * N + col] = __halves2half2(h0, h1);
                *(__half2*)&Cl[(size_t)(row0 + 8) * N + col] = __halves2half2(l0, l1);
            }
        }
    }
}

// ---------------- row softmax over SEQ=4096 -> fp16 split weights ----------------
__global__ void __launch_bounds__(256) softmax_kernel(const float* __restrict__ sc,
                                                      __half* __restrict__ wh,
                                                      __half* __restrict__ wl)
{
    const size_t row = blockIdx.x;
    const float* p = sc + row * (size_t)SEQ;
    const int tid = threadIdx.x;

    float4 v[4];
    float m = -CUDART_INF_F;
    #pragma unroll
    for (int i = 0; i < 4; i++) {
        v[i] = *(const float4*)(p + (size_t)i * 1024 + tid * 4);
        m = fmaxf(m, fmaxf(fmaxf(v[i].x, v[i].y), fmaxf(v[i].z, v[i].w)));
    }

    __shared__ float sred[8];
    #pragma unroll
    for (int o = 16; o > 0; o >>= 1) m = fmaxf(m, __shfl_xor_sync(0xffffffffu, m, o));
    if ((tid & 31) == 0) sred[tid >> 5] = m;
    __syncthreads();
    float rmax = sred[0];
    #pragma unroll
    for (int i = 1; i < 8; i++) rmax = fmaxf(rmax, sred[i]);
    __syncthreads();

    float s = 0.0f;
    #pragma unroll
    for (int i = 0; i < 4; i++) {
        v[i].x = expf(v[i].x - rmax);
        v[i].y = expf(v[i].y - rmax);
        v[i].z = expf(v[i].z - rmax);
        v[i].w = expf(v[i].w - rmax);
        s += (v[i].x + v[i].y) + (v[i].z + v[i].w);
    }
    #pragma unroll
    for (int o = 16; o > 0; o >>= 1) s += __shfl_xor_sync(0xffffffffu, s, o);
    if ((tid & 31) == 0) sred[tid >> 5] = s;
    __syncthreads();
    float rsum = 0.0f;
    #pragma unroll
    for (int i = 0; i < 8; i++) rsum += sred[i];

    const float inv = 1.0f / rsum;
    __half* oh = wh + row * (size_t)SEQ;
    __half* ol = wl + row * (size_t)SEQ;
    #pragma unroll
    for (int i = 0; i < 4; i++) {
        float w0 = v[i].x * inv, w1 = v[i].y * inv, w2 = v[i].z * inv, w3 = v[i].w * inv;
        __half h0, l0, h1, l1, h2, l2, h3, l3;
        split_h(w0, h0, l0); split_h(w1, h1, l1);
        split_h(w2, h2, l2); split_h(w3, h3, l3);
        size_t idx = (size_t)i * 1024 + tid * 4;
        *(__half2*)&oh[idx]     = __halves2half2(h0, h1);
        *(__half2*)&oh[idx + 2] = __halves2half2(h2, h3);
        *(__half2*)&ol[idx]     = __halves2half2(l0, l1);
        *(__half2*)&ol[idx + 2] = __halves2half2(l2, l3);
    }
}

// ---------------- launch ----------------
extern "C" void kernel_launch(void* const* d_in, const int* in_sizes, int n_in,
                              void* d_out, int out_size)
{
    const float* query = (const float*)d_in[0];
    const float* key   = (const float*)d_in[1];
    const float* Wq    = (const float*)d_in[2];
    const float* Wk    = (const float*)d_in[3];
    float* out = (float*)d_out;

    __half *qry_h, *qry_l, *key_h, *key_l, *wqt_h, *wqt_l, *wkt_h, *wkt_l;
    __half *keyT_h, *keyT_l, *q_h, *q_l, *k_h, *k_l, *w_h, *w_l;
    float* sc;
    cudaGetSymbolAddress((void**)&qry_h,  g_qry_h);
    cudaGetSymbolAddress((void**)&qry_l,  g_qry_l);
    cudaGetSymbolAddress((void**)&key_h,  g_key_h);
    cudaGetSymbolAddress((void**)&key_l,  g_key_l);
    cudaGetSymbolAddress((void**)&wqt_h,  g_wqt_h);
    cudaGetSymbolAddress((void**)&wqt_l,  g_wqt_l);
    cudaGetSymbolAddress((void**)&wkt_h,  g_wkt_h);
    cudaGetSymbolAddress((void**)&wkt_l,  g_wkt_l);
    cudaGetSymbolAddress((void**)&keyT_h, g_keyT_h);
    cudaGetSymbolAddress((void**)&keyT_l, g_keyT_l);
    cudaGetSymbolAddress((void**)&q_h,    g_q_h);
    cudaGetSymbolAddress((void**)&q_l,    g_q_l);
    cudaGetSymbolAddress((void**)&k_h,    g_k_h);
    cudaGetSymbolAddress((void**)&k_l,    g_k_l);
    cudaGetSymbolAddress((void**)&sc,     g_sc);
    cudaGetSymbolAddress((void**)&w_h,    g_w_h);
    cudaGetSymbolAddress((void**)&w_l,    g_w_l);

    cudaFuncSetAttribute(gemm_mma, cudaFuncAttributeMaxDynamicSharedMemorySize, DYN_SMEM);

    const long long sQK = (long long)SEQ * DIM;
    const long long sSC = (long long)SEQ * SEQ;
    const long long sKT = (long long)DIM * SEQ;
    const size_t nQK = (size_t)BATCH * SEQ * DIM;

    // 1) fp16 splits of raw inputs
    split_kernel<<<4096, 256>>>(query, qry_h, qry_l, nQK);
    split_kernel<<<4096, 256>>>(key,   key_h, key_l, nQK);

    // 2) transposed + split W  (B operand must be [N,K] K-major)
    transpose_split_kernel<<<dim3(DIM / 32, DIM / 32, 1), dim3(32, 8)>>>(
        Wq, wqt_h, wqt_l, DIM, DIM, 0, 0);
    transpose_split_kernel<<<dim3(DIM / 32, DIM / 32, 1), dim3(32, 8)>>>(
        Wk, wkt_h, wkt_l, DIM, DIM, 0, 0);

    // 3) transposed + split key (V operand): keyT[d][s]
    transpose_split_kernel<<<dim3(DIM / 32, SEQ / 32, BATCH), dim3(32, 8)>>>(
        key, keyT_h, keyT_l, SEQ, DIM, sQK, sKT);

    // 4) projections (epilogue emits fp16 split)
    gemm_mma<<<dim3(DIM / BN, SEQ / BM, BATCH), NTHREADS, DYN_SMEM>>>(
        qry_h, qry_l, wqt_h, wqt_l, nullptr, q_h, q_l, SEQ, DIM, DIM, sQK, 0, sQK);
    gemm_mma<<<dim3(DIM / BN, SEQ / BM, BATCH), NTHREADS, DYN_SMEM>>>(
        key_h, key_l, wkt_h, wkt_l, nullptr, k_h, k_l, SEQ, DIM, DIM, sQK, 0, sQK);

    // 5) scores = q @ k^T (fp32)
    gemm_mma<<<dim3(SEQ / BN, SEQ / BM, BATCH), NTHREADS, DYN_SMEM>>>(
        q_h, q_l, k_h, k_l, sc, nullptr, nullptr, SEQ, SEQ, DIM, sQK, sQK, sSC);

    // 6) softmax -> split weights
    softmax_kernel<<<BATCH * SEQ, 256>>>(sc, w_h, w_l);

    // 7) out = weights @ key  (keyT as [N,K])
    gemm_mma<<<dim3(DIM / BN, SEQ / BM, BATCH), NTHREADS, DYN_SMEM>>>(
        w_h, w_l, keyT_h, keyT_l, out, nullptr, nullptr, SEQ, DIM, SEQ, sSC, sKT, sQK);
}

// round 8
// speedup vs baseline: 3.6347x; 1.3211x over previous
#include <cuda_runtime.h>
#include <cuda_fp16.h>
#include <math_constants.h>
#include <cstdint>
#include <cstddef>

#define BATCH 2
#define SEQ   4096
#define DIM   512

// ---------------- scratch (allocation-free: __device__ globals) ----------------
__device__ __half g_qry_h[(size_t)BATCH * SEQ * DIM];
__device__ __half g_qry_l[(size_t)BATCH * SEQ * DIM];
__device__ __half g_key_h[(size_t)BATCH * SEQ * DIM];
__device__ __half g_key_l[(size_t)BATCH * SEQ * DIM];
__device__ __half g_wqt_h[(size_t)DIM * DIM];
__device__ __half g_wqt_l[(size_t)DIM * DIM];
__device__ __half g_wkt_h[(size_t)DIM * DIM];
__device__ __half g_wkt_l[(size_t)DIM * DIM];
__device__ __half g_keyT_h[(size_t)BATCH * DIM * SEQ];
__device__ __half g_keyT_l[(size_t)BATCH * DIM * SEQ];
__device__ __half g_q_h[(size_t)BATCH * SEQ * DIM];
__device__ __half g_q_l[(size_t)BATCH * SEQ * DIM];
__device__ __half g_k_h[(size_t)BATCH * SEQ * DIM];
__device__ __half g_k_l[(size_t)BATCH * SEQ * DIM];
__device__ float  g_sc [(size_t)BATCH * SEQ * SEQ];
__device__ __half g_w_h[(size_t)BATCH * SEQ * SEQ];

// ---------------- helpers ----------------
__device__ __forceinline__ uint32_t s2u(const void* p) {
    uint32_t a;
    asm("{ .reg .u64 t; cvta.to.shared.u64 t, %1; cvt.u32.u64 %0, t; }" : "=r"(a) : "l"(p));
    return a;
}

__device__ __forceinline__ void ldsm_x4(uint32_t& r0, uint32_t& r1, uint32_t& r2, uint32_t& r3,
                                        uint32_t addr) {
    asm volatile("ldmatrix.sync.aligned.m8n8.x4.shared.b16 {%0,%1,%2,%3}, [%4];"
                 : "=r"(r0), "=r"(r1), "=r"(r2), "=r"(r3) : "r"(addr));
}

__device__ __forceinline__ void mma16816(float* d, const uint32_t* a, const uint32_t* b) {
    asm volatile(
        "mma.sync.aligned.m16n8k16.row.col.f32.f16.f16.f32 "
        "{%0,%1,%2,%3},{%4,%5,%6,%7},{%8,%9},{%0,%1,%2,%3};"
        : "+f"(d[0]), "+f"(d[1]), "+f"(d[2]), "+f"(d[3])
        : "r"(a[0]), "r"(a[1]), "r"(a[2]), "r"(a[3]), "r"(b[0]), "r"(b[1]));
}

__device__ __forceinline__ void split_h(float v, __half& h, __half& l) {
    h = __float2half_rn(v);
    l = __float2half_rn(v - __half2float(h));
}

// ---------------- prep kernels ----------------
__global__ void split_kernel(const float* __restrict__ in, __half* __restrict__ oh,
                             __half* __restrict__ ol, size_t n) {
    for (size_t i = (size_t)blockIdx.x * blockDim.x + threadIdx.x; i < n;
         i += (size_t)gridDim.x * blockDim.x) {
        __half h, l; split_h(in[i], h, l);
        oh[i] = h; ol[i] = l;
    }
}

// out[c][r] = in[r][c], fp16 hi/lo split. in: [R,C] row-major, out: [C,R].
__global__ void transpose_split_kernel(const float* __restrict__ in, __half* __restrict__ oh,
                                       __half* __restrict__ ol, int R, int C,
                                       long long sIn, long long sOut) {
    __shared__ float t[32][33];
    const int bz = blockIdx.z;
    in += (size_t)bz * sIn;
    oh += (size_t)bz * sOut;
    ol += (size_t)bz * sOut;
    const int c0 = blockIdx.x * 32, r0 = blockIdx.y * 32;
    const int tx = threadIdx.x, ty = threadIdx.y;  // 32 x 8
    #pragma unroll
    for (int j = 0; j < 32; j += 8)
        t[ty + j][tx] = in[(size_t)(r0 + ty + j) * C + c0 + tx];
    __syncthreads();
    #pragma unroll
    for (int j = 0; j < 32; j += 8) {
        size_t idx = (size_t)(c0 + ty + j) * R + r0 + tx;
        __half h, l; split_h(t[tx][ty + j], h, l);
        oh[idx] = h; ol[idx] = l;
    }
}

// ---------------- mma.sync fp16 GEMM:  C[M,N] = A[M,K] * B[N,K]^T -------------
// NPASS==3: A,B are exact (hi,lo) fp16 splits; compensated hh + hl + lh.
// NPASS==1: plain fp16 GEMM (hi tiles only; Al/Bl unused).
// Cf != nullptr -> fp32 out; else fp16 split to (Ch, Cl).
// 256x128 CTA tile, 512 threads (8 warps M x 2 warps N; warp tile 32x64).
#define BM 256
#define BN 128
#define BK 32
#define STAGES 3
#define ATILE_B (BM * BK * 2)            // 16 KB (fp16)
#define BTILE_B (BN * BK * 2)            // 8 KB
#define STAGE_B (2 * ATILE_B + 2 * BTILE_B)   // 48 KB
#define DYN_SMEM (STAGES * STAGE_B)           // 144 KB
#define NTHREADS 512

// swizzled byte offset of 16B chunk (row, ch) in a [rows][32 fp16] tile (64B rows)
__device__ __forceinline__ uint32_t sw_off(int row, int ch) {
    return (uint32_t)(row * 64 + ((ch ^ ((row >> 1) & 3)) << 4));
}

template <int NPASS>
__global__ void __launch_bounds__(NTHREADS, 1) gemm_mma(
    const __half* __restrict__ Ah, const __half* __restrict__ Al,
    const __half* __restrict__ Bh, const __half* __restrict__ Bl,
    float* __restrict__ Cf, __half* __restrict__ Ch, __half* __restrict__ Cl,
    int M, int N, int K, long long sA, long long sB, long long sC)
{
    extern __shared__ char smem[];
    const int tid  = threadIdx.x;
    const int lane = tid & 31;
    const int wid  = tid >> 5;
    const int wm   = wid & 7;      // 8 warps over M -> 32 rows each
    const int wn   = wid >> 3;     // 2 warps over N -> 64 cols each
    const int bz = blockIdx.z;
    Ah += (size_t)bz * sA;
    Bh += (size_t)bz * sB;
    if (NPASS == 3) { Al += (size_t)bz * sA; Bl += (size_t)bz * sB; }
    if (Cf) Cf += (size_t)bz * sC;
    if (Ch) { Ch += (size_t)bz * sC; Cl += (size_t)bz * sC; }
    const int bm = blockIdx.y * BM;
    const int bn = blockIdx.x * BN;
    const uint32_t sbase = s2u(smem);
    const int NC = K / BK;

    float acc[2][8][4];
    #pragma unroll
    for (int a = 0; a < 2; a++)
        #pragma unroll
        for (int b = 0; b < 8; b++)
            #pragma unroll
            for (int c = 0; c < 4; c++) acc[a][b][c] = 0.0f;

    // ---- loader ----
    // NPASS==3: Ah/Al 1024 16B-chunks each + Bh/Bl 512 each = 3072 (6 iters)
    // NPASS==1: Ah 1024 + Bh 512 = 1536 (3 iters)
    auto load_chunk = [&](int chunk) {
        const uint32_t sb = sbase + (chunk % STAGES) * STAGE_B;
        constexpr int J = (NPASS == 3) ? 6 : 3;
        #pragma unroll
        for (int j = 0; j < J; j++) {
            int g = tid + NTHREADS * j;
            const __half* base;
            uint32_t dst;
            int row, c;
            if (NPASS == 3) {
                if (g < 2048) {                 // A side
                    int t = g >> 10;            // 0: Ah, 1: Al
                    int u = g & 1023;
                    row = u >> 2; c = u & 3;
                    base = t ? Al : Ah;
                    dst = sb + t * ATILE_B + sw_off(row, c);
                    base += (size_t)(bm + row) * K + chunk * BK + c * 8;
                } else {                        // B side
                    int b2 = g - 2048;
                    int t = b2 >> 9;            // 0: Bh, 1: Bl
                    int u = b2 & 511;
                    row = u >> 2; c = u & 3;
                    base = t ? Bl : Bh;
                    dst = sb + 2 * ATILE_B + t * BTILE_B + sw_off(row, c);
                    base += (size_t)(bn + row) * K + chunk * BK + c * 8;
                }
            } else {
                if (g < 1024) {                 // Ah
                    row = g >> 2; c = g & 3;
                    base = Ah;
                    dst = sb + sw_off(row, c);
                    base += (size_t)(bm + row) * K + chunk * BK + c * 8;
                } else {                        // Bh
                    int u = g - 1024;
                    row = u >> 2; c = u & 3;
                    base = Bh;
                    dst = sb + 2 * ATILE_B + sw_off(row, c);
                    base += (size_t)(bn + row) * K + chunk * BK + c * 8;
                }
            }
            asm volatile("cp.async.cg.shared.global [%0], [%1], 16;" :: "r"(dst), "l"(base));
        }
        asm volatile("cp.async.commit_group;" ::: "memory");
    };

    load_chunk(0);
    if (NC > 1) load_chunk(1); else asm volatile("cp.async.commit_group;" ::: "memory");

    for (int i = 0; i < NC; i++) {
        asm volatile("cp.async.wait_group 1;" ::: "memory");
        __syncthreads();
        if (i + 2 < NC) load_chunk(i + 2);
        else asm volatile("cp.async.commit_group;" ::: "memory");

        const uint32_t sb  = sbase + (i % STAGES) * STAGE_B;
        const uint32_t sAh = sb;
        const uint32_t sAl = sb + ATILE_B;
        const uint32_t sBh = sb + 2 * ATILE_B;
        const uint32_t sBl = sb + 2 * ATILE_B + BTILE_B;
        const int q = lane >> 3, r = lane & 7;

        #pragma unroll
        for (int ks = 0; ks < 2; ks++) {
            uint32_t a_h[2][4], a_l[2][4];
            // A frags: mats (m0-7,klo)(m8-15,klo)(m0-7,khi)(m8-15,khi)
            #pragma unroll
            for (int mf = 0; mf < 2; mf++) {
                int row = wm * 32 + mf * 16 + ((q & 1) << 3) + r;
                int ch  = 2 * ks + (q >> 1);
                uint32_t ad = sw_off(row, ch);
                ldsm_x4(a_h[mf][0], a_h[mf][1], a_h[mf][2], a_h[mf][3], sAh + ad);
                if (NPASS == 3)
                    ldsm_x4(a_l[mf][0], a_l[mf][1], a_l[mf][2], a_l[mf][3], sAl + ad);
            }
            // B frags streamed per 16-col group to bound register pressure
            #pragma unroll
            for (int np = 0; np < 4; np++) {
                uint32_t b_h[2][2], b_l[2][2];
                int row = wn * 64 + np * 16 + ((q >> 1) << 3) + r;
                int ch  = 2 * ks + (q & 1);
                uint32_t bd = sw_off(row, ch);
                ldsm_x4(b_h[0][0], b_h[0][1], b_h[1][0], b_h[1][1], sBh + bd);
                if (NPASS == 3)
                    ldsm_x4(b_l[0][0], b_l[0][1], b_l[1][0], b_l[1][1], sBl + bd);
                #pragma unroll
                for (int mf = 0; mf < 2; mf++)
                    #pragma unroll
                    for (int nn = 0; nn < 2; nn++) {
                        float* d = acc[mf][2 * np + nn];
                        mma16816(d, a_h[mf], b_h[nn]);
                        if (NPASS == 3) {
                            mma16816(d, a_h[mf], b_l[nn]);
                            mma16816(d, a_l[mf], b_h[nn]);
                        }
                    }
            }
        }
        __syncthreads();
    }

    // ---- epilogue: fragment direct stores ----
    const int lr = lane >> 2;          // 0..7
    const int lc = (lane & 3) * 2;     // 0,2,4,6
    #pragma unroll
    for (int mf = 0; mf < 2; mf++) {
        #pragma unroll
        for (int nf = 0; nf < 8; nf++) {
            int row0 = bm + wm * 32 + mf * 16 + lr;
            int col  = bn + wn * 64 + nf * 8 + lc;
            float* d = acc[mf][nf];
            if (Cf) {
                *(float2*)&Cf[(size_t)row0 * N + col]       = make_float2(d[0], d[1]);
                *(float2*)&Cf[(size_t)(row0 + 8) * N + col] = make_float2(d[2], d[3]);
            } else {
                __half h0, l0, h1, l1;
                split_h(d[0], h0, l0); split_h(d[1], h1, l1);
                *(__half2*)&Ch[(size_t)row0 * N + col] = __halves2half2(h0, h1);
                *(__half2*)&Cl[(size_t)row0 * N + col] = __halves2half2(l0, l1);
                split_h(d[2], h0, l0); split_h(d[3], h1, l1);
                *(__half2*)&Ch[(size_t)(row0 + 8) * N + col] = __halves2half2(h0, h1);
                *(__half2*)&Cl[(size_t)(row0 + 8) * N + col] = __halves2half2(l0, l1);
            }
        }
    }
}

// ---------------- row softmax over SEQ=4096 -> plain fp16 weights ----------------
__global__ void __launch_bounds__(256) softmax_kernel(const float* __restrict__ sc,
                                                      __half* __restrict__ wh)
{
    const size_t row = blockIdx.x;
    const float* p = sc + row * (size_t)SEQ;
    const int tid = threadIdx.x;

    float4 v[4];
    float m = -CUDART_INF_F;
    #pragma unroll
    for (int i = 0; i < 4; i++) {
        v[i] = *(const float4*)(p + (size_t)i * 1024 + tid * 4);
        m = fmaxf(m, fmaxf(fmaxf(v[i].x, v[i].y), fmaxf(v[i].z, v[i].w)));
    }

    __shared__ float sred[8];
    #pragma unroll
    for (int o = 16; o > 0; o >>= 1) m = fmaxf(m, __shfl_xor_sync(0xffffffffu, m, o));
    if ((tid & 31) == 0) sred[tid >> 5] = m;
    __syncthreads();
    float rmax = sred[0];
    #pragma unroll
    for (int i = 1; i < 8; i++) rmax = fmaxf(rmax, sred[i]);
    __syncthreads();

    float s = 0.0f;
    #pragma unroll
    for (int i = 0; i < 4; i++) {
        v[i].x = expf(v[i].x - rmax);
        v[i].y = expf(v[i].y - rmax);
        v[i].z = expf(v[i].z - rmax);
        v[i].w = expf(v[i].w - rmax);
        s += (v[i].x + v[i].y) + (v[i].z + v[i].w);
    }
    #pragma unroll
    for (int o = 16; o > 0; o >>= 1) s += __shfl_xor_sync(0xffffffffu, s, o);
    if ((tid & 31) == 0) sred[tid >> 5] = s;
    __syncthreads();
    float rsum = 0.0f;
    #pragma unroll
    for (int i = 0; i < 8; i++) rsum += sred[i];

    const float inv = 1.0f / rsum;
    __half* oh = wh + row * (size_t)SEQ;
    #pragma unroll
    for (int i = 0; i < 4; i++) {
        __half h0 = __float2half_rn(v[i].x * inv);
        __half h1 = __float2half_rn(v[i].y * inv);
        __half h2 = __float2half_rn(v[i].z * inv);
        __half h3 = __float2half_rn(v[i].w * inv);
        size_t idx = (size_t)i * 1024 + tid * 4;
        *(__half2*)&oh[idx]     = __halves2half2(h0, h1);
        *(__half2*)&oh[idx + 2] = __halves2half2(h2, h3);
    }
}

// ---------------- launch ----------------
extern "C" void kernel_launch(void* const* d_in, const int* in_sizes, int n_in,
                              void* d_out, int out_size)
{
    const float* query = (const float*)d_in[0];
    const float* key   = (const float*)d_in[1];
    const float* Wq    = (const float*)d_in[2];
    const float* Wk    = (const float*)d_in[3];
    float* out = (float*)d_out;

    __half *qry_h, *qry_l, *key_h, *key_l, *wqt_h, *wqt_l, *wkt_h, *wkt_l;
    __half *keyT_h, *keyT_l, *q_h, *q_l, *k_h, *k_l, *w_h;
    float* sc;
    cudaGetSymbolAddress((void**)&qry_h,  g_qry_h);
    cudaGetSymbolAddress((void**)&qry_l,  g_qry_l);
    cudaGetSymbolAddress((void**)&key_h,  g_key_h);
    cudaGetSymbolAddress((void**)&key_l,  g_key_l);
    cudaGetSymbolAddress((void**)&wqt_h,  g_wqt_h);
    cudaGetSymbolAddress((void**)&wqt_l,  g_wqt_l);
    cudaGetSymbolAddress((void**)&wkt_h,  g_wkt_h);
    cudaGetSymbolAddress((void**)&wkt_l,  g_wkt_l);
    cudaGetSymbolAddress((void**)&keyT_h, g_keyT_h);
    cudaGetSymbolAddress((void**)&keyT_l, g_keyT_l);
    cudaGetSymbolAddress((void**)&q_h,    g_q_h);
    cudaGetSymbolAddress((void**)&q_l,    g_q_l);
    cudaGetSymbolAddress((void**)&k_h,    g_k_h);
    cudaGetSymbolAddress((void**)&k_l,    g_k_l);
    cudaGetSymbolAddress((void**)&sc,     g_sc);
    cudaGetSymbolAddress((void**)&w_h,    g_w_h);

    cudaFuncSetAttribute(gemm_mma<3>, cudaFuncAttributeMaxDynamicSharedMemorySize, DYN_SMEM);
    cudaFuncSetAttribute(gemm_mma<1>, cudaFuncAttributeMaxDynamicSharedMemorySize, DYN_SMEM);

    const long long sQK = (long long)SEQ * DIM;
    const long long sSC = (long long)SEQ * SEQ;
    const long long sKT = (long long)DIM * SEQ;
    const size_t nQK = (size_t)BATCH * SEQ * DIM;

    // 1) fp16 splits of raw inputs
    split_kernel<<<4096, 256>>>(query, qry_h, qry_l, nQK);
    split_kernel<<<4096, 256>>>(key,   key_h, key_l, nQK);

    // 2) transposed + split W  (B operand must be [N,K] K-major)
    transpose_split_kernel<<<dim3(DIM / 32, DIM / 32, 1), dim3(32, 8)>>>(
        Wq, wqt_h, wqt_l, DIM, DIM, 0, 0);
    transpose_split_kernel<<<dim3(DIM / 32, DIM / 32, 1), dim3(32, 8)>>>(
        Wk, wkt_h, wkt_l, DIM, DIM, 0, 0);

    // 3) transposed + split key (V operand): keyT[d][s]
    transpose_split_kernel<<<dim3(DIM / 32, SEQ / 32, BATCH), dim3(32, 8)>>>(
        key, keyT_h, keyT_l, SEQ, DIM, sQK, sKT);

    // 4) projections (3-pass; epilogue emits fp16 split)
    gemm_mma<3><<<dim3(DIM / BN, SEQ / BM, BATCH), NTHREADS, DYN_SMEM>>>(
        qry_h, qry_l, wqt_h, wqt_l, nullptr, q_h, q_l, SEQ, DIM, DIM, sQK, 0, sQK);
    gemm_mma<3><<<dim3(DIM / BN, SEQ / BM, BATCH), NTHREADS, DYN_SMEM>>>(
        key_h, key_l, wkt_h, wkt_l, nullptr, k_h, k_l, SEQ, DIM, DIM, sQK, 0, sQK);

    // 5) scores = q @ k^T (3-pass, fp32 out)
    gemm_mma<3><<<dim3(SEQ / BN, SEQ / BM, BATCH), NTHREADS, DYN_SMEM>>>(
        q_h, q_l, k_h, k_l, sc, nullptr, nullptr, SEQ, SEQ, DIM, sQK, sQK, sSC);

    // 6) softmax -> plain fp16 weights
    softmax_kernel<<<BATCH * SEQ, 256>>>(sc, w_h);

    // 7) out = weights @ key (1-pass plain fp16; errors not amplified here)
    gemm_mma<1><<<dim3(DIM / BN, SEQ / BM, BATCH), NTHREADS, DYN_SMEM>>>(
        w_h, nullptr, keyT_h, nullptr, out, nullptr, nullptr, SEQ, DIM, SEQ, sSC, sKT, sQK);
}

// round 9
// speedup vs baseline: 3.7172x; 1.0227x over previous
#include <cuda_runtime.h>
#include <cuda_fp16.h>
#include <math_constants.h>
#include <cstdint>
#include <cstddef>

#define BATCH 2
#define SEQ   4096
#define DIM   512

// ---------------- scratch (allocation-free: __device__ globals) ----------------
__device__ __half g_qry_h[(size_t)BATCH * SEQ * DIM];
__device__ __half g_qry_l[(size_t)BATCH * SEQ * DIM];
__device__ __half g_key_h[(size_t)BATCH * SEQ * DIM];
__device__ __half g_key_l[(size_t)BATCH * SEQ * DIM];
__device__ __half g_wqt_h[(size_t)DIM * DIM];
__device__ __half g_wqt_l[(size_t)DIM * DIM];
__device__ __half g_wkt_h[(size_t)DIM * DIM];
__device__ __half g_wkt_l[(size_t)DIM * DIM];
__device__ __half g_keyT_h[(size_t)BATCH * DIM * SEQ];
__device__ __half g_keyT_l[(size_t)BATCH * DIM * SEQ];
__device__ __half g_q_h[(size_t)BATCH * SEQ * DIM];
__device__ __half g_q_l[(size_t)BATCH * SEQ * DIM];
__device__ __half g_k_h[(size_t)BATCH * SEQ * DIM];
__device__ __half g_k_l[(size_t)BATCH * SEQ * DIM];
__device__ float  g_sc [(size_t)BATCH * SEQ * SEQ];
__device__ __half g_w_h[(size_t)BATCH * SEQ * SEQ];

// ---------------- helpers ----------------
__device__ __forceinline__ uint32_t s2u(const void* p) {
    uint32_t a;
    asm("{ .reg .u64 t; cvta.to.shared.u64 t, %1; cvt.u32.u64 %0, t; }" : "=r"(a) : "l"(p));
    return a;
}

__device__ __forceinline__ void ldsm_x4(uint32_t& r0, uint32_t& r1, uint32_t& r2, uint32_t& r3,
                                        uint32_t addr) {
    asm volatile("ldmatrix.sync.aligned.m8n8.x4.shared.b16 {%0,%1,%2,%3}, [%4];"
                 : "=r"(r0), "=r"(r1), "=r"(r2), "=r"(r3) : "r"(addr));
}

__device__ __forceinline__ void mma16816(float* d, const uint32_t* a, const uint32_t* b) {
    asm volatile(
        "mma.sync.aligned.m16n8k16.row.col.f32.f16.f16.f32 "
        "{%0,%1,%2,%3},{%4,%5,%6,%7},{%8,%9},{%0,%1,%2,%3};"
        : "+f"(d[0]), "+f"(d[1]), "+f"(d[2]), "+f"(d[3])
        : "r"(a[0]), "r"(a[1]), "r"(a[2]), "r"(a[3]), "r"(b[0]), "r"(b[1]));
}

__device__ __forceinline__ void split_h(float v, __half& h, __half& l) {
    h = __float2half_rn(v);
    l = __float2half_rn(v - __half2float(h));
}

// ---------------- prep kernels ----------------
__global__ void split_kernel(const float* __restrict__ in, __half* __restrict__ oh,
                             __half* __restrict__ ol, size_t n) {
    for (size_t i = (size_t)blockIdx.x * blockDim.x + threadIdx.x; i < n;
         i += (size_t)gridDim.x * blockDim.x) {
        __half h, l; split_h(in[i], h, l);
        oh[i] = h; ol[i] = l;
    }
}

// out[c][r] = in[r][c], fp16 hi/lo split. in: [R,C] row-major, out: [C,R].
__global__ void transpose_split_kernel(const float* __restrict__ in, __half* __restrict__ oh,
                                       __half* __restrict__ ol, int R, int C,
                                       long long sIn, long long sOut) {
    __shared__ float t[32][33];
    const int bz = blockIdx.z;
    in += (size_t)bz * sIn;
    oh += (size_t)bz * sOut;
    ol += (size_t)bz * sOut;
    const int c0 = blockIdx.x * 32, r0 = blockIdx.y * 32;
    const int tx = threadIdx.x, ty = threadIdx.y;  // 32 x 8
    #pragma unroll
    for (int j = 0; j < 32; j += 8)
        t[ty + j][tx] = in[(size_t)(r0 + ty + j) * C + c0 + tx];
    __syncthreads();
    #pragma unroll
    for (int j = 0; j < 32; j += 8) {
        size_t idx = (size_t)(c0 + ty + j) * R + r0 + tx;
        __half h, l; split_h(t[tx][ty + j], h, l);
        oh[idx] = h; ol[idx] = l;
    }
}

// ---------------- mma.sync fp16 GEMM:  C[M,N] = A[M,K] * B[N,K]^T -------------
// NPASS==3: A,B are exact (hi,lo) fp16 splits; compensated hh + hl + lh.
// NPASS==1: plain fp16 GEMM (hi tiles only; Al/Bl unused).
// Cf != nullptr -> fp32 out; else fp16 split to (Ch, Cl).
// 256x128 CTA tile, 512 threads (8 warps M x 2 warps N; warp tile 32x64).
// 4-stage cp.async pipeline, ONE __syncthreads per iteration.
#define BM 256
#define BN 128
#define BK 32
#define STAGES 4
#define ATILE_B (BM * BK * 2)            // 16 KB (fp16)
#define BTILE_B (BN * BK * 2)            // 8 KB
#define STAGE_B (2 * ATILE_B + 2 * BTILE_B)   // 48 KB
#define DYN_SMEM (STAGES * STAGE_B)           // 192 KB
#define NTHREADS 512

// swizzled byte offset of 16B chunk (row, ch) in a [rows][32 fp16] tile (64B rows)
__device__ __forceinline__ uint32_t sw_off(int row, int ch) {
    return (uint32_t)(row * 64 + ((ch ^ ((row >> 1) & 3)) << 4));
}

template <int NPASS>
__global__ void __launch_bounds__(NTHREADS, 1) gemm_mma(
    const __half* __restrict__ Ah, const __half* __restrict__ Al,
    const __half* __restrict__ Bh, const __half* __restrict__ Bl,
    float* __restrict__ Cf, __half* __restrict__ Ch, __half* __restrict__ Cl,
    int M, int N, int K, long long sA, long long sB, long long sC)
{
    extern __shared__ char smem[];
    const int tid  = threadIdx.x;
    const int lane = tid & 31;
    const int wid  = tid >> 5;
    const int wm   = wid & 7;      // 8 warps over M -> 32 rows each
    const int wn   = wid >> 3;     // 2 warps over N -> 64 cols each
    const int bz = blockIdx.z;
    Ah += (size_t)bz * sA;
    Bh += (size_t)bz * sB;
    if (NPASS == 3) { Al += (size_t)bz * sA; Bl += (size_t)bz * sB; }
    if (Cf) Cf += (size_t)bz * sC;
    if (Ch) { Ch += (size_t)bz * sC; Cl += (size_t)bz * sC; }
    const int bm = blockIdx.y * BM;
    const int bn = blockIdx.x * BN;
    const uint32_t sbase = s2u(smem);
    const int NC = K / BK;

    float acc[2][8][4];
    #pragma unroll
    for (int a = 0; a < 2; a++)
        #pragma unroll
        for (int b = 0; b < 8; b++)
            #pragma unroll
            for (int c = 0; c < 4; c++) acc[a][b][c] = 0.0f;

    // ---- loader ----
    // NPASS==3: Ah/Al 1024 16B-chunks each + Bh/Bl 512 each = 3072 (6 iters)
    // NPASS==1: Ah 1024 + Bh 512 = 1536 (3 iters)
    auto load_chunk = [&](int chunk) {
        const uint32_t sb = sbase + (chunk % STAGES) * STAGE_B;
        constexpr int J = (NPASS == 3) ? 6 : 3;
        #pragma unroll
        for (int j = 0; j < J; j++) {
            int g = tid + NTHREADS * j;
            const __half* base;
            uint32_t dst;
            int row, c;
            if (NPASS == 3) {
                if (g < 2048) {                 // A side
                    int t = g >> 10;            // 0: Ah, 1: Al
                    int u = g & 1023;
                    row = u >> 2; c = u & 3;
                    base = t ? Al : Ah;
                    dst = sb + t * ATILE_B + sw_off(row, c);
                    base += (size_t)(bm + row) * K + chunk * BK + c * 8;
                } else {                        // B side
                    int b2 = g - 2048;
                    int t = b2 >> 9;            // 0: Bh, 1: Bl
                    int u = b2 & 511;
                    row = u >> 2; c = u & 3;
                    base = t ? Bl : Bh;
                    dst = sb + 2 * ATILE_B + t * BTILE_B + sw_off(row, c);
                    base += (size_t)(bn + row) * K + chunk * BK + c * 8;
                }
            } else {
                if (g < 1024) {                 // Ah
                    row = g >> 2; c = g & 3;
                    base = Ah;
                    dst = sb + sw_off(row, c);
                    base += (size_t)(bm + row) * K + chunk * BK + c * 8;
                } else {                        // Bh
                    int u = g - 1024;
                    row = u >> 2; c = u & 3;
                    base = Bh;
                    dst = sb + 2 * ATILE_B + sw_off(row, c);
                    base += (size_t)(bn + row) * K + chunk * BK + c * 8;
                }
            }
            asm volatile("cp.async.cg.shared.global [%0], [%1], 16;" :: "r"(dst), "l"(base));
        }
        asm volatile("cp.async.commit_group;" ::: "memory");
    };

    // prologue: 3 chunks in flight
    #pragma unroll
    for (int p = 0; p < 3; p++) {
        if (p < NC) load_chunk(p);
        else asm volatile("cp.async.commit_group;" ::: "memory");
    }

    for (int i = 0; i < NC; i++) {
        asm volatile("cp.async.wait_group 2;" ::: "memory");   // chunk i complete
        __syncthreads();                                       // visible; stage (i-1)%4 free
        if (i + 3 < NC) load_chunk(i + 3);                     // into freed stage, overlaps MMA
        else asm volatile("cp.async.commit_group;" ::: "memory");

        const uint32_t sb  = sbase + (i % STAGES) * STAGE_B;
        const uint32_t sAh = sb;
        const uint32_t sAl = sb + ATILE_B;
        const uint32_t sBh = sb + 2 * ATILE_B;
        const uint32_t sBl = sb + 2 * ATILE_B + BTILE_B;
        const int q = lane >> 3, r = lane & 7;

        #pragma unroll
        for (int ks = 0; ks < 2; ks++) {
            uint32_t a_h[2][4], a_l[2][4];
            // A frags: mats (m0-7,klo)(m8-15,klo)(m0-7,khi)(m8-15,khi)
            #pragma unroll
            for (int mf = 0; mf < 2; mf++) {
                int row = wm * 32 + mf * 16 + ((q & 1) << 3) + r;
                int ch  = 2 * ks + (q >> 1);
                uint32_t ad = sw_off(row, ch);
                ldsm_x4(a_h[mf][0], a_h[mf][1], a_h[mf][2], a_h[mf][3], sAh + ad);
                if (NPASS == 3)
                    ldsm_x4(a_l[mf][0], a_l[mf][1], a_l[mf][2], a_l[mf][3], sAl + ad);
            }
            // B frags streamed per 16-col group to bound register pressure
            #pragma unroll
            for (int np = 0; np < 4; np++) {
                uint32_t b_h[2][2], b_l[2][2];
                int row = wn * 64 + np * 16 + ((q >> 1) << 3) + r;
                int ch  = 2 * ks + (q & 1);
                uint32_t bd = sw_off(row, ch);
                ldsm_x4(b_h[0][0], b_h[0][1], b_h[1][0], b_h[1][1], sBh + bd);
                if (NPASS == 3)
                    ldsm_x4(b_l[0][0], b_l[0][1], b_l[1][0], b_l[1][1], sBl + bd);
                #pragma unroll
                for (int mf = 0; mf < 2; mf++)
                    #pragma unroll
                    for (int nn = 0; nn < 2; nn++) {
                        float* d = acc[mf][2 * np + nn];
                        mma16816(d, a_h[mf], b_h[nn]);
                        if (NPASS == 3) {
                            mma16816(d, a_h[mf], b_l[nn]);
                            mma16816(d, a_l[mf], b_h[nn]);
                        }
                    }
            }
        }
    }
    __syncthreads();

    // ---- epilogue: fragment direct stores ----
    const int lr = lane >> 2;          // 0..7
    const int lc = (lane & 3) * 2;     // 0,2,4,6
    #pragma unroll
    for (int mf = 0; mf < 2; mf++) {
        #pragma unroll
        for (int nf = 0; nf < 8; nf++) {
            int row0 = bm + wm * 32 + mf * 16 + lr;
            int col  = bn + wn * 64 + nf * 8 + lc;
            float* d = acc[mf][nf];
            if (Cf) {
                *(float2*)&Cf[(size_t)row0 * N + col]       = make_float2(d[0], d[1]);
                *(float2*)&Cf[(size_t)(row0 + 8) * N + col] = make_float2(d[2], d[3]);
            } else {
                __half h0, l0, h1, l1;
                split_h(d[0], h0, l0); split_h(d[1], h1, l1);
                *(__half2*)&Ch[(size_t)row0 * N + col] = __halves2half2(h0, h1);
                *(__half2*)&Cl[(size_t)row0 * N + col] = __halves2half2(l0, l1);
                split_h(d[2], h0, l0); split_h(d[3], h1, l1);
                *(__half2*)&Ch[(size_t)(row0 + 8) * N + col] = __halves2half2(h0, h1);
                *(__half2*)&Cl[(size_t)(row0 + 8) * N + col] = __halves2half2(l0, l1);
            }
        }
    }
}

// ---------------- row softmax over SEQ=4096 -> plain fp16 weights ----------------
__global__ void __launch_bounds__(256) softmax_kernel(const float* __restrict__ sc,
                                                      __half* __restrict__ wh)
{
    const size_t row = blockIdx.x;
    const float* p = sc + row * (size_t)SEQ;
    const int tid = threadIdx.x;

    float4 v[4];
    float m = -CUDART_INF_F;
    #pragma unroll
    for (int i = 0; i < 4; i++) {
        v[i] = *(const float4*)(p + (size_t)i * 1024 + tid * 4);
        m = fmaxf(m, fmaxf(fmaxf(v[i].x, v[i].y), fmaxf(v[i].z, v[i].w)));
    }

    __shared__ float sred[8];
    #pragma unroll
    for (int o = 16; o > 0; o >>= 1) m = fmaxf(m, __shfl_xor_sync(0xffffffffu, m, o));
    if ((tid & 31) == 0) sred[tid >> 5] = m;
    __syncthreads();
    float rmax = sred[0];
    #pragma unroll
    for (int i = 1; i < 8; i++) rmax = fmaxf(rmax, sred[i]);
    __syncthreads();

    float s = 0.0f;
    #pragma unroll
    for (int i = 0; i < 4; i++) {
        v[i].x = expf(v[i].x - rmax);
        v[i].y = expf(v[i].y - rmax);
        v[i].z = expf(v[i].z - rmax);
        v[i].w = expf(v[i].w - rmax);
        s += (v[i].x + v[i].y) + (v[i].z + v[i].w);
    }
    #pragma unroll
    for (int o = 16; o > 0; o >>= 1) s += __shfl_xor_sync(0xffffffffu, s, o);
    if ((tid & 31) == 0) sred[tid >> 5] = s;
    __syncthreads();
    float rsum = 0.0f;
    #pragma unroll
    for (int i = 0; i < 8; i++) rsum += sred[i];

    const float inv = 1.0f / rsum;
    __half* oh = wh + row * (size_t)SEQ;
    #pragma unroll
    for (int i = 0; i < 4; i++) {
        __half h0 = __float2half_rn(v[i].x * inv);
        __half h1 = __float2half_rn(v[i].y * inv);
        __half h2 = __float2half_rn(v[i].z * inv);
        __half h3 = __float2half_rn(v[i].w * inv);
        size_t idx = (size_t)i * 1024 + tid * 4;
        *(__half2*)&oh[idx]     = __halves2half2(h0, h1);
        *(__half2*)&oh[idx + 2] = __halves2half2(h2, h3);
    }
}

// ---------------- launch ----------------
extern "C" void kernel_launch(void* const* d_in, const int* in_sizes, int n_in,
                              void* d_out, int out_size)
{
    const float* query = (const float*)d_in[0];
    const float* key   = (const float*)d_in[1];
    const float* Wq    = (const float*)d_in[2];
    const float* Wk    = (const float*)d_in[3];
    float* out = (float*)d_out;

    __half *qry_h, *qry_l, *key_h, *key_l, *wqt_h, *wqt_l, *wkt_h, *wkt_l;
    __half *keyT_h, *keyT_l, *q_h, *q_l, *k_h, *k_l, *w_h;
    float* sc;
    cudaGetSymbolAddress((void**)&qry_h,  g_qry_h);
    cudaGetSymbolAddress((void**)&qry_l,  g_qry_l);
    cudaGetSymbolAddress((void**)&key_h,  g_key_h);
    cudaGetSymbolAddress((void**)&key_l,  g_key_l);
    cudaGetSymbolAddress((void**)&wqt_h,  g_wqt_h);
    cudaGetSymbolAddress((void**)&wqt_l,  g_wqt_l);
    cudaGetSymbolAddress((void**)&wkt_h,  g_wkt_h);
    cudaGetSymbolAddress((void**)&wkt_l,  g_wkt_l);
    cudaGetSymbolAddress((void**)&keyT_h, g_keyT_h);
    cudaGetSymbolAddress((void**)&keyT_l, g_keyT_l);
    cudaGetSymbolAddress((void**)&q_h,    g_q_h);
    cudaGetSymbolAddress((void**)&q_l,    g_q_l);
    cudaGetSymbolAddress((void**)&k_h,    g_k_h);
    cudaGetSymbolAddress((void**)&k_l,    g_k_l);
    cudaGetSymbolAddress((void**)&sc,     g_sc);
    cudaGetSymbolAddress((void**)&w_h,    g_w_h);

    cudaFuncSetAttribute(gemm_mma<3>, cudaFuncAttributeMaxDynamicSharedMemorySize, DYN_SMEM);
    cudaFuncSetAttribute(gemm_mma<1>, cudaFuncAttributeMaxDynamicSharedMemorySize, DYN_SMEM);

    const long long sQK = (long long)SEQ * DIM;
    const long long sSC = (long long)SEQ * SEQ;
    const long long sKT = (long long)DIM * SEQ;
    const size_t nQK = (size_t)BATCH * SEQ * DIM;

    // 1) fp16 splits of raw inputs
    split_kernel<<<4096, 256>>>(query, qry_h, qry_l, nQK);
    split_kernel<<<4096, 256>>>(key,   key_h, key_l, nQK);

    // 2) transposed + split W  (B operand must be [N,K] K-major)
    transpose_split_kernel<<<dim3(DIM / 32, DIM / 32, 1), dim3(32, 8)>>>(
        Wq, wqt_h, wqt_l, DIM, DIM, 0, 0);
    transpose_split_kernel<<<dim3(DIM / 32, DIM / 32, 1), dim3(32, 8)>>>(
        Wk, wkt_h, wkt_l, DIM, DIM, 0, 0);

    // 3) transposed + split key (V operand): keyT[d][s]
    transpose_split_kernel<<<dim3(DIM / 32, SEQ / 32, BATCH), dim3(32, 8)>>>(
        key, keyT_h, keyT_l, SEQ, DIM, sQK, sKT);

    // 4) projections (3-pass; epilogue emits fp16 split)
    gemm_mma<3><<<dim3(DIM / BN, SEQ / BM, BATCH), NTHREADS, DYN_SMEM>>>(
        qry_h, qry_l, wqt_h, wqt_l, nullptr, q_h, q_l, SEQ, DIM, DIM, sQK, 0, sQK);
    gemm_mma<3><<<dim3(DIM / BN, SEQ / BM, BATCH), NTHREADS, DYN_SMEM>>>(
        key_h, key_l, wkt_h, wkt_l, nullptr, k_h, k_l, SEQ, DIM, DIM, sQK, 0, sQK);

    // 5) scores = q @ k^T (3-pass, fp32 out)
    gemm_mma<3><<<dim3(SEQ / BN, SEQ / BM, BATCH), NTHREADS, DYN_SMEM>>>(
        q_h, q_l, k_h, k_l, sc, nullptr, nullptr, SEQ, SEQ, DIM, sQK, sQK, sSC);

    // 6) softmax -> plain fp16 weights
    softmax_kernel<<<BATCH * SEQ, 256>>>(sc, w_h);

    // 7) out = weights @ key (1-pass plain fp16; errors not amplified here)
    gemm_mma<1><<<dim3(DIM / BN, SEQ / BM, BATCH), NTHREADS, DYN_SMEM>>>(
        w_h, nullptr, keyT_h, nullptr, out, nullptr, nullptr, SEQ, DIM, SEQ, sSC, sKT, sQK);
}